// round 15
// baseline (speedup 1.0000x reference)
#include <cuda_runtime.h>
#include <cuda_fp16.h>
#include <mma.h>
#include <cstdint>

using namespace nvcuda;

// Problem constants: 50000 nodes, 1.6M edges, 128->64->32->1
#define MAXN 50000
#define MAXE 1600000
#define C1 64
#define C2 32
#define CAP 128          // per-node bucket capacity (max degree ~66 at 6 sigma)

// Scratch (static __device__ — no allocation allowed).
__device__ __align__(256) int    g_srcs[(size_t)MAXN * CAP];   // 25.6 MB buckets
__device__ __align__(256) __half g_g1h[(size_t)MAXN * C1];     // pre-scaled by dinv
__device__ __align__(256) __half g_g2h[(size_t)MAXN * C2];     // pre-scaled by dinv
__device__ __align__(256) __half g_w1h[128 * C1];
__device__ float g_dinv[MAXN];
__device__ int   g_cursor[MAXN];                 // becomes degree after scatter
__device__ int   g_is64;

__device__ __forceinline__ int load_idx(const void* ei, int is64, long long pos) {
    if (is64) return (int)((const long long*)ei)[pos];
    return ((const int*)ei)[pos];
}

// ---------------------------------------------------------------------------
// packed f32x2 helpers
__device__ __forceinline__ void addp(unsigned long long& a, float2 f) {
    unsigned long long b;
    asm("mov.b64 %0, {%1, %2};" : "=l"(b) : "f"(f.x), "f"(f.y));
    asm("add.rn.f32x2 %0, %1, %2;" : "=l"(a) : "l"(a), "l"(b));
}
__device__ __forceinline__ unsigned long long addp2(unsigned long long a,
                                                    unsigned long long b) {
    unsigned long long r;
    asm("add.rn.f32x2 %0, %1, %2;" : "=l"(r) : "l"(a), "l"(b));
    return r;
}
__device__ __forceinline__ float2 unpack_f2(unsigned long long a) {
    float2 f;
    asm("mov.b64 {%0, %1}, %2;" : "=f"(f.x), "=f"(f.y) : "l"(a));
    return f;
}
__device__ __forceinline__ void add_h8p(unsigned long long* acc, uint4 v) {
    __half2* p = reinterpret_cast<__half2*>(&v);
    #pragma unroll
    for (int k = 0; k < 4; k++) addp(acc[k], __half22float2(p[k]));
}
__device__ __forceinline__ void add_h8p2(unsigned long long* acc, uint4 v0, uint4 v1) {
    __half2* p0 = reinterpret_cast<__half2*>(&v0);
    __half2* p1 = reinterpret_cast<__half2*>(&v1);
    #pragma unroll
    for (int k = 0; k < 4; k++)
        addp(acc[k], __half22float2(__hadd2(p0[k], p1[k])));
}
__device__ __forceinline__ int sel4(int4 a, int s) {
    return s == 0 ? a.x : (s == 1 ? a.y : (s == 2 ? a.z : a.w));
}

// ---------------------------------------------------------------------------
// init: zero cursors + dtype sniff + W1 -> fp16
__global__ void init_kernel(const void* __restrict__ ei,
                            const float* __restrict__ W1, int nodes) {
    int i = blockIdx.x * blockDim.x + threadIdx.x;
    if (i < nodes) g_cursor[i] = 0;
    if (blockIdx.x == 0) {
        for (int k = threadIdx.x; k < 128 * C1; k += 256)
            g_w1h[k] = __float2half(W1[k]);
        if (threadIdx.x == 0) {
            const unsigned int* p = (const unsigned int*)ei;
            int is64 = 1;
            #pragma unroll
            for (int k = 0; k < 32; k++) {
                if (p[2 * k + 1] != 0u) { is64 = 0; break; }
            }
            g_is64 = is64;
        }
    }
}

// ---------------------------------------------------------------------------
// Bucket scatter (4 edges/thread). After this, g_cursor[n] == degree(n).
__global__ __launch_bounds__(256) void scatter_kernel(
    const void* __restrict__ ei, int E)
{
    int e0 = (blockIdx.x * 256 + threadIdx.x) * 4;
    if (e0 >= E) return;
    int is64 = g_is64;
    if (!is64 && e0 + 4 <= E) {
        const int4 s4 = *reinterpret_cast<const int4*>((const int*)ei + e0);
        const int4 d4 = *reinterpret_cast<const int4*>((const int*)ei + E + e0);
        int p0 = atomicAdd(&g_cursor[d4.x], 1);
        int p1 = atomicAdd(&g_cursor[d4.y], 1);
        int p2 = atomicAdd(&g_cursor[d4.z], 1);
        int p3 = atomicAdd(&g_cursor[d4.w], 1);
        if (p0 < CAP) g_srcs[(size_t)d4.x * CAP + p0] = s4.x;
        if (p1 < CAP) g_srcs[(size_t)d4.y * CAP + p1] = s4.y;
        if (p2 < CAP) g_srcs[(size_t)d4.z * CAP + p2] = s4.z;
        if (p3 < CAP) g_srcs[(size_t)d4.w * CAP + p3] = s4.w;
    } else {
        for (int k = 0; k < 4 && e0 + k < E; k++) {
            int src = load_idx(ei, is64, e0 + k);
            int dst = load_idx(ei, is64, (long long)E + e0 + k);
            int pos = atomicAdd(&g_cursor[dst], 1);
            if (pos < CAP) g_srcs[(size_t)dst * CAP + pos] = src;
        }
    }
}

// ---------------------------------------------------------------------------
// Tensor-core GEMM1 with inline dinv epilogue (cursor==degree after scatter):
//   g1h = fp16(dinv * (x @ W1)),  g_dinv written as side effect.
__global__ __launch_bounds__(256) void gemm1_kernel(
    const float* __restrict__ X, int nodes)
{
    __shared__ __align__(16) char buf[49152];
    __half* Xh  = reinterpret_cast<__half*>(buf);           // [128][128] 32KB
    __half* W1s = reinterpret_cast<__half*>(buf + 32768);   // [128][64]  16KB
    float*  Cs  = reinterpret_cast<float*>(buf);            // overlays Xh

    int tid = threadIdx.x;
    int rowBase = blockIdx.x * 128;

    #pragma unroll
    for (int i = 0; i < 16; i++) {
        int idx = tid + i * 256;
        int row = idx >> 5;
        int k4  = idx & 31;
        float4 v = (rowBase + row < nodes)
            ? reinterpret_cast<const float4*>(X)[(size_t)(rowBase + row) * 32 + k4]
            : make_float4(0.f, 0.f, 0.f, 0.f);
        __half2 h0 = __floats2half2_rn(v.x, v.y);
        __half2 h1 = __floats2half2_rn(v.z, v.w);
        uint2 o;
        o.x = *reinterpret_cast<unsigned int*>(&h0);
        o.y = *reinterpret_cast<unsigned int*>(&h1);
        *reinterpret_cast<uint2*>(&Xh[row * 128 + k4 * 4]) = o;
    }
    #pragma unroll
    for (int i = 0; i < 4; i++) {
        int u = tid + i * 256;
        reinterpret_cast<uint4*>(W1s)[u] =
            reinterpret_cast<const uint4*>(g_w1h)[u];
    }
    __syncthreads();

    int warp = tid >> 5;
    wmma::fragment<wmma::accumulator, 16, 16, 16, float> c[4];
    #pragma unroll
    for (int n = 0; n < 4; n++) wmma::fill_fragment(c[n], 0.0f);

    #pragma unroll
    for (int k0 = 0; k0 < 8; k0++) {
        wmma::fragment<wmma::matrix_a, 16, 16, 16, __half, wmma::row_major> a;
        wmma::load_matrix_sync(a, Xh + warp * 16 * 128 + k0 * 16, 128);
        #pragma unroll
        for (int n = 0; n < 4; n++) {
            wmma::fragment<wmma::matrix_b, 16, 16, 16, __half, wmma::row_major> b;
            wmma::load_matrix_sync(b, W1s + k0 * 16 * 64 + n * 16, 64);
            wmma::mma_sync(c[n], a, b, c[n]);
        }
    }
    __syncthreads();
    #pragma unroll
    for (int n = 0; n < 4; n++)
        wmma::store_matrix_sync(Cs + warp * 16 * 64 + n * 16, c[n], 64,
                                wmma::mem_row_major);
    __syncthreads();

    #pragma unroll
    for (int i = 0; i < 4; i++) {
        int u = tid * 4 + i;
        int row = u >> 3;
        int c4  = u & 7;
        int grow = rowBase + row;
        if (grow >= nodes) continue;
        float d = rsqrtf((float)g_cursor[grow] + 1.0f);
        if (c4 == 0) g_dinv[grow] = d;
        const float* src = &Cs[row * 64 + c4 * 8];
        __half2 h0 = __floats2half2_rn(src[0] * d, src[1] * d);
        __half2 h1 = __floats2half2_rn(src[2] * d, src[3] * d);
        __half2 h2 = __floats2half2_rn(src[4] * d, src[5] * d);
        __half2 h3 = __floats2half2_rn(src[6] * d, src[7] * d);
        uint4 o;
        o.x = *reinterpret_cast<unsigned int*>(&h0);
        o.y = *reinterpret_cast<unsigned int*>(&h1);
        o.z = *reinterpret_cast<unsigned int*>(&h2);
        o.w = *reinterpret_cast<unsigned int*>(&h3);
        reinterpret_cast<uint4*>(g_g1h)[(size_t)grow * 8 + c4] = o;
    }
}

// ---------------------------------------------------------------------------
// Fused gather1 + relu + GEMM2 — ONE WARP PER NODE (no degree divergence).
// Phase A: 32 lanes = 4 edge-slots x 8 channel-chunks; 8 edges per iter.
// Phase B: 16 nodes/block x 32 cols, 1 col/thread.
#define HS 68
__global__ __launch_bounds__(512, 4) void gather1_gemm2_kernel(
    const float* __restrict__ b1, const float* __restrict__ W2, int nodes)
{
    __shared__ float h_s[16 * HS];
    __shared__ float W2s[C1 * C2];
    __shared__ float b1s[C1];

    int tid = threadIdx.x;
    for (int i = tid; i < C1 * C2; i += 512) W2s[i] = W2[i];
    if (tid < C1) b1s[tid] = b1[tid];

    int warp = tid >> 5;
    int lane = tid & 31;
    int slot = lane >> 3;       // edge slot 0..3
    int c    = lane & 7;        // channel chunk (uint4 of 8 halves)
    int node = blockIdx.x * 16 + warp;

    if (node < nodes) {
        float d = g_dinv[node];
        int deg = min(g_cursor[node], CAP);
        const int* sp = &g_srcs[(size_t)node * CAP];
        const int4* sp4 = reinterpret_cast<const int4*>(sp);
        const uint4* G = reinterpret_cast<const uint4*>(g_g1h);

        unsigned long long acc[4];
        #pragma unroll
        for (int j = 0; j < 4; j++) acc[j] = 0ull;

        int ngrp = deg >> 3;               // groups of 8 edges
        for (int g = 0; g < ngrp; g++) {
            int4 a = sp4[2 * g];           // broadcast load (same addr all lanes)
            int4 b = sp4[2 * g + 1];
            int e0 = sel4(a, slot);
            int e1 = sel4(b, slot);
            uint4 v0 = G[e0 * 8 + c];
            uint4 v1 = G[e1 * 8 + c];
            add_h8p2(acc, v0, v1);
        }
        for (int i = (ngrp << 3) + slot; i < deg; i += 4)
            add_h8p(acc, G[sp[i] * 8 + c]);
        if (slot == 0)
            add_h8p(acc, G[node * 8 + c]);   // self term (pre-scaled)

        // reduce across the 4 edge-slots (lanes c, 8+c, 16+c, 24+c)
        #pragma unroll
        for (int j = 0; j < 4; j++) {
            acc[j] = addp2(acc[j], __shfl_xor_sync(0xffffffffu, acc[j], 8));
            acc[j] = addp2(acc[j], __shfl_xor_sync(0xffffffffu, acc[j], 16));
        }
        if (slot == 0) {
            float* hp = &h_s[warp * HS + c * 8];
            #pragma unroll
            for (int j = 0; j < 4; j++) {
                float2 f = unpack_f2(acc[j]);
                hp[j * 2 + 0] = fmaxf(fmaf(d, f.x, b1s[c * 8 + j * 2 + 0]), 0.0f);
                hp[j * 2 + 1] = fmaxf(fmaf(d, f.y, b1s[c * 8 + j * 2 + 1]), 0.0f);
            }
        }
    }
    __syncthreads();

    // Phase B: node = tid>>5, col = tid&31
    int nodeB = blockIdx.x * 16 + (tid >> 5);
    if (nodeB >= nodes) return;
    int col = tid & 31;
    float d2 = g_dinv[nodeB];
    const float4* hr4 = reinterpret_cast<const float4*>(&h_s[(tid >> 5) * HS]);
    float o = 0.0f;
    #pragma unroll
    for (int k4 = 0; k4 < 16; k4++) {
        float4 h4 = hr4[k4];                 // broadcast within warp
        o = fmaf(h4.x, W2s[(k4 * 4 + 0) * C2 + col], o);
        o = fmaf(h4.y, W2s[(k4 * 4 + 1) * C2 + col], o);
        o = fmaf(h4.z, W2s[(k4 * 4 + 2) * C2 + col], o);
        o = fmaf(h4.w, W2s[(k4 * 4 + 3) * C2 + col], o);
    }
    g_g2h[(size_t)nodeB * C2 + col] = __float2half(o * d2);
}

// ---------------------------------------------------------------------------
// Fused gather2 + head — ONE WARP PER NODE.
// 32 lanes = 8 edge-slots x 4 channel-chunks; 16 edges per iter.
__global__ __launch_bounds__(512, 4) void gather2_final_kernel(
    const float* __restrict__ b2, const float* __restrict__ Wh,
    const float* __restrict__ bh, float* __restrict__ out, int nodes)
{
    __shared__ float b2s[C2];
    __shared__ float Whs[C2];
    int tid = threadIdx.x;
    if (tid < C2) { b2s[tid] = b2[tid]; Whs[tid] = Wh[tid]; }
    __syncthreads();

    int warp = tid >> 5;
    int lane = tid & 31;
    int slot = lane >> 2;       // edge slot 0..7
    int c    = lane & 3;        // channel chunk (uint4 of 8 halves)
    int node = blockIdx.x * 16 + warp;
    if (node >= nodes) return;

    int deg = min(g_cursor[node], CAP);
    const int* sp = &g_srcs[(size_t)node * CAP];
    const int4* sp4 = reinterpret_cast<const int4*>(sp);
    const uint4* G = reinterpret_cast<const uint4*>(g_g2h);

    unsigned long long acc[4];
    #pragma unroll
    for (int j = 0; j < 4; j++) acc[j] = 0ull;

    int quad = slot >> 2;                 // 0 or 1
    int qs   = slot & 3;
    int ngrp = deg >> 4;                  // groups of 16 edges
    for (int g = 0; g < ngrp; g++) {
        int4 a = sp4[4 * g + quad];
        int4 b = sp4[4 * g + 2 + quad];
        int e0 = sel4(a, qs);
        int e1 = sel4(b, qs);
        uint4 v0 = G[e0 * 4 + c];
        uint4 v1 = G[e1 * 4 + c];
        add_h8p2(acc, v0, v1);
    }
    for (int i = (ngrp << 4) + slot; i < deg; i += 8)
        add_h8p(acc, G[sp[i] * 4 + c]);
    if (slot == 0)
        add_h8p(acc, G[node * 4 + c]);     // self term

    // reduce across 8 edge-slots
    #pragma unroll
    for (int j = 0; j < 4; j++) {
        acc[j] = addp2(acc[j], __shfl_xor_sync(0xffffffffu, acc[j], 4));
        acc[j] = addp2(acc[j], __shfl_xor_sync(0xffffffffu, acc[j], 8));
        acc[j] = addp2(acc[j], __shfl_xor_sync(0xffffffffu, acc[j], 16));
    }

    float p = 0.0f;
    if (slot == 0) {                       // lanes 0..3 hold chunks 0..3
        float d = g_dinv[node];
        #pragma unroll
        for (int j = 0; j < 4; j++) {
            float2 f = unpack_f2(acc[j]);
            int ch = c * 8 + j * 2;
            float v0 = fmaf(d, f.x, b2s[ch]);
            float v1 = fmaf(d, f.y, b2s[ch + 1]);
            p = fmaf(fmaxf(v0, 0.0f), Whs[ch], p);
            p = fmaf(fmaxf(v1, 0.0f), Whs[ch + 1], p);
        }
    }
    p += __shfl_xor_sync(0xffffffffu, p, 1);
    p += __shfl_xor_sync(0xffffffffu, p, 2);
    if (lane == 0) out[node] = p + bh[0];
}

// ---------------------------------------------------------------------------
extern "C" void kernel_launch(void* const* d_in, const int* in_sizes, int n_in,
                              void* d_out, int out_size)
{
    const float* x  = (const float*)d_in[0];
    const void*  ei = d_in[1];
    const float* W1 = (const float*)d_in[2];
    const float* b1 = (const float*)d_in[3];
    const float* W2 = (const float*)d_in[4];
    const float* b2 = (const float*)d_in[5];
    const float* Wh = (const float*)d_in[6];
    const float* bh = (const float*)d_in[7];
    float* out = (float*)d_out;

    int nodes = in_sizes[0] / 128;
    int E = in_sizes[1] / 2;
    int nb = (nodes + 255) / 256;               // 196
    int degB = (E / 4 + 255) / 256;             // 1563 (4 edges/thread)
    int gemmB = (nodes + 127) / 128;            // 391
    int gatB = (nodes + 15) / 16;               // 3125 (16 nodes/block)

    init_kernel<<<nb, 256>>>(ei, W1, nodes);
    scatter_kernel<<<degB, 256>>>(ei, E);
    gemm1_kernel<<<gemmB, 256>>>(x, nodes);
    gather1_gemm2_kernel<<<gatB, 512>>>(b1, W2, nodes);
    gather2_final_kernel<<<gatB, 512>>>(b2, Wh, bh, out, nodes);
}

// round 16
// speedup vs baseline: 1.2195x; 1.2195x over previous
#include <cuda_runtime.h>
#include <cuda_fp16.h>
#include <mma.h>
#include <cstdint>

using namespace nvcuda;

// Problem constants: 50000 nodes, 1.6M edges, 128->64->32->1
#define MAXN 50000
#define MAXE 1600000
#define C1 64
#define C2 32
#define CAP 128          // per-node bucket capacity (max degree ~66 at 6 sigma)

// Scratch (static __device__ — no allocation allowed).
// INVARIANT: g_cursor is all-zero at every kernel_launch entry. It is
// zero-initialized at module load, and gather2_final (the last reader)
// re-zeroes each node's cursor after use, restoring the invariant for the
// next call / graph replay.
__device__ __align__(256) int    g_srcs[(size_t)MAXN * CAP];   // 25.6 MB buckets
__device__ __align__(256) __half g_g1h[(size_t)MAXN * C1];     // pre-scaled by dinv
__device__ __align__(256) __half g_g2h[(size_t)MAXN * C2];     // pre-scaled by dinv
__device__ float g_dinv[MAXN];
__device__ int   g_cursor[MAXN];                 // becomes degree after scatter

__device__ __forceinline__ int sniff_is64(const void* ei) {
    const unsigned int* p = (const unsigned int*)ei;
    int is64 = 1;
    #pragma unroll
    for (int k = 0; k < 32; k++)
        if (p[2 * k + 1] != 0u) { is64 = 0; break; }
    return is64;
}

__device__ __forceinline__ int load_idx(const void* ei, int is64, long long pos) {
    if (is64) return (int)((const long long*)ei)[pos];
    return ((const int*)ei)[pos];
}

// ---------------------------------------------------------------------------
// packed f32x2 helpers
__device__ __forceinline__ void addp(unsigned long long& a, float2 f) {
    unsigned long long b;
    asm("mov.b64 %0, {%1, %2};" : "=l"(b) : "f"(f.x), "f"(f.y));
    asm("add.rn.f32x2 %0, %1, %2;" : "=l"(a) : "l"(a), "l"(b));
}
__device__ __forceinline__ float2 unpack_f2(unsigned long long a) {
    float2 f;
    asm("mov.b64 {%0, %1}, %2;" : "=f"(f.x), "=f"(f.y) : "l"(a));
    return f;
}
__device__ __forceinline__ void add_h8p(unsigned long long* acc, uint4 v) {
    __half2* p = reinterpret_cast<__half2*>(&v);
    #pragma unroll
    for (int k = 0; k < 4; k++) addp(acc[k], __half22float2(p[k]));
}
__device__ __forceinline__ void add_h8p2(unsigned long long* acc, uint4 v0, uint4 v1) {
    __half2* p0 = reinterpret_cast<__half2*>(&v0);
    __half2* p1 = reinterpret_cast<__half2*>(&v1);
    #pragma unroll
    for (int k = 0; k < 4; k++)
        addp(acc[k], __half22float2(__hadd2(p0[k], p1[k])));
}

// ---------------------------------------------------------------------------
// Bucket scatter (4 edges/thread, per-block dtype sniff).
// Relies on the g_cursor==0 entry invariant. After this, cursor == degree.
__global__ __launch_bounds__(256) void scatter_kernel(
    const void* __restrict__ ei, int E)
{
    __shared__ int s_is64;
    if (threadIdx.x == 0) s_is64 = sniff_is64(ei);
    __syncthreads();
    int is64 = s_is64;

    int e0 = (blockIdx.x * 256 + threadIdx.x) * 4;
    if (e0 >= E) return;
    if (!is64 && e0 + 4 <= E) {
        const int4 s4 = *reinterpret_cast<const int4*>((const int*)ei + e0);
        const int4 d4 = *reinterpret_cast<const int4*>((const int*)ei + E + e0);
        int p0 = atomicAdd(&g_cursor[d4.x], 1);
        int p1 = atomicAdd(&g_cursor[d4.y], 1);
        int p2 = atomicAdd(&g_cursor[d4.z], 1);
        int p3 = atomicAdd(&g_cursor[d4.w], 1);
        if (p0 < CAP) g_srcs[(size_t)d4.x * CAP + p0] = s4.x;
        if (p1 < CAP) g_srcs[(size_t)d4.y * CAP + p1] = s4.y;
        if (p2 < CAP) g_srcs[(size_t)d4.z * CAP + p2] = s4.z;
        if (p3 < CAP) g_srcs[(size_t)d4.w * CAP + p3] = s4.w;
    } else {
        for (int k = 0; k < 4 && e0 + k < E; k++) {
            int src = load_idx(ei, is64, e0 + k);
            int dst = load_idx(ei, is64, (long long)E + e0 + k);
            int pos = atomicAdd(&g_cursor[dst], 1);
            if (pos < CAP) g_srcs[(size_t)dst * CAP + pos] = src;
        }
    }
}

// ---------------------------------------------------------------------------
// Tensor-core GEMM1 with inline dinv epilogue (cursor==degree after scatter):
//   g1h = fp16(dinv * (x @ W1)),  g_dinv written as side effect.
// W1 converted fp32->fp16 directly from global (no staging kernel needed).
__global__ __launch_bounds__(256) void gemm1_kernel(
    const float* __restrict__ X, const float* __restrict__ W1, int nodes)
{
    __shared__ __align__(16) char buf[49152];
    __half* Xh  = reinterpret_cast<__half*>(buf);           // [128][128] 32KB
    __half* W1s = reinterpret_cast<__half*>(buf + 32768);   // [128][64]  16KB
    float*  Cs  = reinterpret_cast<float*>(buf);            // overlays Xh

    int tid = threadIdx.x;
    int rowBase = blockIdx.x * 128;

    #pragma unroll
    for (int i = 0; i < 16; i++) {
        int idx = tid + i * 256;
        int row = idx >> 5;
        int k4  = idx & 31;
        float4 v = (rowBase + row < nodes)
            ? reinterpret_cast<const float4*>(X)[(size_t)(rowBase + row) * 32 + k4]
            : make_float4(0.f, 0.f, 0.f, 0.f);
        __half2 h0 = __floats2half2_rn(v.x, v.y);
        __half2 h1 = __floats2half2_rn(v.z, v.w);
        uint2 o;
        o.x = *reinterpret_cast<unsigned int*>(&h0);
        o.y = *reinterpret_cast<unsigned int*>(&h1);
        *reinterpret_cast<uint2*>(&Xh[row * 128 + k4 * 4]) = o;
    }
    // W1 fp32 -> fp16 smem (8192 elems = 2048 float4-loads of 4 halves)
    #pragma unroll
    for (int i = 0; i < 8; i++) {
        int u = tid + i * 256;              // float4 index, 2048 total
        float4 w = reinterpret_cast<const float4*>(W1)[u];
        __half2 h0 = __floats2half2_rn(w.x, w.y);
        __half2 h1 = __floats2half2_rn(w.z, w.w);
        uint2 o;
        o.x = *reinterpret_cast<unsigned int*>(&h0);
        o.y = *reinterpret_cast<unsigned int*>(&h1);
        *reinterpret_cast<uint2*>(&W1s[u * 4]) = o;
    }
    __syncthreads();

    int warp = tid >> 5;
    wmma::fragment<wmma::accumulator, 16, 16, 16, float> c[4];
    #pragma unroll
    for (int n = 0; n < 4; n++) wmma::fill_fragment(c[n], 0.0f);

    #pragma unroll
    for (int k0 = 0; k0 < 8; k0++) {
        wmma::fragment<wmma::matrix_a, 16, 16, 16, __half, wmma::row_major> a;
        wmma::load_matrix_sync(a, Xh + warp * 16 * 128 + k0 * 16, 128);
        #pragma unroll
        for (int n = 0; n < 4; n++) {
            wmma::fragment<wmma::matrix_b, 16, 16, 16, __half, wmma::row_major> b;
            wmma::load_matrix_sync(b, W1s + k0 * 16 * 64 + n * 16, 64);
            wmma::mma_sync(c[n], a, b, c[n]);
        }
    }
    __syncthreads();
    #pragma unroll
    for (int n = 0; n < 4; n++)
        wmma::store_matrix_sync(Cs + warp * 16 * 64 + n * 16, c[n], 64,
                                wmma::mem_row_major);
    __syncthreads();

    #pragma unroll
    for (int i = 0; i < 4; i++) {
        int u = tid * 4 + i;
        int row = u >> 3;
        int c4  = u & 7;
        int grow = rowBase + row;
        if (grow >= nodes) continue;
        float d = rsqrtf((float)g_cursor[grow] + 1.0f);
        if (c4 == 0) g_dinv[grow] = d;
        const float* src = &Cs[row * 64 + c4 * 8];
        __half2 h0 = __floats2half2_rn(src[0] * d, src[1] * d);
        __half2 h1 = __floats2half2_rn(src[2] * d, src[3] * d);
        __half2 h2 = __floats2half2_rn(src[4] * d, src[5] * d);
        __half2 h3 = __floats2half2_rn(src[6] * d, src[7] * d);
        uint4 o;
        o.x = *reinterpret_cast<unsigned int*>(&h0);
        o.y = *reinterpret_cast<unsigned int*>(&h1);
        o.z = *reinterpret_cast<unsigned int*>(&h2);
        o.w = *reinterpret_cast<unsigned int*>(&h3);
        reinterpret_cast<uint4*>(g_g1h)[(size_t)grow * 8 + c4] = o;
    }
}

// ---------------------------------------------------------------------------
// Fused gather1 + relu + GEMM2 (R14 layout — proven equilibrium).
#define HS 68
__global__ __launch_bounds__(512, 4) void gather1_gemm2_kernel(
    const float* __restrict__ b1, const float* __restrict__ W2, int nodes)
{
    __shared__ float h_s[64 * HS];
    __shared__ float W2s[C1 * C2];
    __shared__ float b1s[C1];

    int tid = threadIdx.x;
    for (int i = tid; i < C1 * C2; i += 512) W2s[i] = W2[i];
    if (tid < C1) b1s[tid] = b1[tid];

    int nl = tid >> 3;
    int c  = tid & 7;
    int node = blockIdx.x * 64 + nl;
    float d = 0.0f;

    if (node < nodes) {
        d = g_dinv[node];
        int deg = min(g_cursor[node], CAP);
        const int* sp = &g_srcs[(size_t)node * CAP];
        const int4* sp4 = reinterpret_cast<const int4*>(sp);
        const uint4* G = reinterpret_cast<const uint4*>(g_g1h);

        unsigned long long acc[4];
        #pragma unroll
        for (int j = 0; j < 4; j++) acc[j] = 0ull;

        int ngrp = deg >> 2;
        if (ngrp > 0) {
            int4 s = sp4[0];
            #pragma unroll 2
            for (int g = 0; g < ngrp; g++) {
                int4 sn = sp4[min(g + 1, ngrp - 1)];
                uint4 v0 = G[s.x * 8 + c];
                uint4 v1 = G[s.y * 8 + c];
                uint4 v2 = G[s.z * 8 + c];
                uint4 v3 = G[s.w * 8 + c];
                add_h8p2(acc, v0, v1);
                add_h8p2(acc, v2, v3);
                s = sn;
            }
        }
        for (int i = ngrp << 2; i < deg; i++) {
            add_h8p(acc, G[sp[i] * 8 + c]);
        }
        add_h8p(acc, G[node * 8 + c]);   // self term (pre-scaled)

        float* hp = &h_s[nl * HS + c * 8];
        #pragma unroll
        for (int j = 0; j < 4; j++) {
            float2 f = unpack_f2(acc[j]);
            hp[j * 2 + 0] = fmaxf(fmaf(d, f.x, b1s[c * 8 + j * 2 + 0]), 0.0f);
            hp[j * 2 + 1] = fmaxf(fmaf(d, f.y, b1s[c * 8 + j * 2 + 1]), 0.0f);
        }
    }
    __syncthreads();

    if (node >= nodes) return;
    float o0 = 0.f, o1 = 0.f, o2 = 0.f, o3 = 0.f;
    const float4* hr4 = reinterpret_cast<const float4*>(&h_s[nl * HS]);
    const float4* W24 = reinterpret_cast<const float4*>(W2s);
    #pragma unroll
    for (int k4 = 0; k4 < 16; k4++) {
        float4 h4 = hr4[k4];
        float4 wa = W24[(k4 * 4 + 0) * 8 + c];
        float4 wb = W24[(k4 * 4 + 1) * 8 + c];
        float4 wc = W24[(k4 * 4 + 2) * 8 + c];
        float4 wd = W24[(k4 * 4 + 3) * 8 + c];
        o0 = fmaf(h4.x, wa.x, o0); o1 = fmaf(h4.x, wa.y, o1);
        o2 = fmaf(h4.x, wa.z, o2); o3 = fmaf(h4.x, wa.w, o3);
        o0 = fmaf(h4.y, wb.x, o0); o1 = fmaf(h4.y, wb.y, o1);
        o2 = fmaf(h4.y, wb.z, o2); o3 = fmaf(h4.y, wb.w, o3);
        o0 = fmaf(h4.z, wc.x, o0); o1 = fmaf(h4.z, wc.y, o1);
        o2 = fmaf(h4.z, wc.z, o2); o3 = fmaf(h4.z, wc.w, o3);
        o0 = fmaf(h4.w, wd.x, o0); o1 = fmaf(h4.w, wd.y, o1);
        o2 = fmaf(h4.w, wd.z, o2); o3 = fmaf(h4.w, wd.w, o3);
    }
    __half2 h0 = __floats2half2_rn(o0 * d, o1 * d);
    __half2 h1 = __floats2half2_rn(o2 * d, o3 * d);
    uint2 o;
    o.x = *reinterpret_cast<unsigned int*>(&h0);
    o.y = *reinterpret_cast<unsigned int*>(&h1);
    reinterpret_cast<uint2*>(g_g2h)[(size_t)node * 8 + c] = o;
}

// ---------------------------------------------------------------------------
// Fused gather2 + head (R14 layout). LAST reader of g_cursor: restores the
// all-zero cursor invariant for the next kernel_launch call.
__global__ __launch_bounds__(512, 4) void gather2_final_kernel(
    const float* __restrict__ b2, const float* __restrict__ Wh,
    const float* __restrict__ bh, float* __restrict__ out, int nodes)
{
    __shared__ float b2s[C2];
    __shared__ float Whs[C2];
    int tid = threadIdx.x;
    if (tid < C2) { b2s[tid] = b2[tid]; Whs[tid] = Wh[tid]; }
    __syncthreads();

    int nl = tid >> 2;
    int c  = tid & 3;
    int node = blockIdx.x * 128 + nl;
    if (node >= nodes) return;

    int deg = min(g_cursor[node], CAP);
    if (c == 0) g_cursor[node] = 0;      // restore entry invariant
    const int* sp = &g_srcs[(size_t)node * CAP];
    const int4* sp4 = reinterpret_cast<const int4*>(sp);
    const uint4* G = reinterpret_cast<const uint4*>(g_g2h);

    unsigned long long acc[4];
    #pragma unroll
    for (int j = 0; j < 4; j++) acc[j] = 0ull;

    int ngrp = deg >> 2;
    if (ngrp > 0) {
        int4 s = sp4[0];
        #pragma unroll 2
        for (int g = 0; g < ngrp; g++) {
            int4 sn = sp4[min(g + 1, ngrp - 1)];
            uint4 v0 = G[s.x * 4 + c];
            uint4 v1 = G[s.y * 4 + c];
            uint4 v2 = G[s.z * 4 + c];
            uint4 v3 = G[s.w * 4 + c];
            add_h8p2(acc, v0, v1);
            add_h8p2(acc, v2, v3);
            s = sn;
        }
    }
    for (int i = ngrp << 2; i < deg; i++) {
        add_h8p(acc, G[sp[i] * 4 + c]);
    }
    add_h8p(acc, G[node * 4 + c]);     // self term

    float d = g_dinv[node];
    float p = 0.0f;
    #pragma unroll
    for (int j = 0; j < 4; j++) {
        float2 f = unpack_f2(acc[j]);
        int ch = c * 8 + j * 2;
        float v0 = fmaf(d, f.x, b2s[ch]);
        float v1 = fmaf(d, f.y, b2s[ch + 1]);
        p = fmaf(fmaxf(v0, 0.0f), Whs[ch], p);
        p = fmaf(fmaxf(v1, 0.0f), Whs[ch + 1], p);
    }
    p += __shfl_xor_sync(0xffffffffu, p, 1);
    p += __shfl_xor_sync(0xffffffffu, p, 2);
    if (c == 0) out[node] = p + bh[0];
}

// ---------------------------------------------------------------------------
extern "C" void kernel_launch(void* const* d_in, const int* in_sizes, int n_in,
                              void* d_out, int out_size)
{
    const float* x  = (const float*)d_in[0];
    const void*  ei = d_in[1];
    const float* W1 = (const float*)d_in[2];
    const float* b1 = (const float*)d_in[3];
    const float* W2 = (const float*)d_in[4];
    const float* b2 = (const float*)d_in[5];
    const float* Wh = (const float*)d_in[6];
    const float* bh = (const float*)d_in[7];
    float* out = (float*)d_out;

    int nodes = in_sizes[0] / 128;
    int E = in_sizes[1] / 2;
    int degB = (E / 4 + 255) / 256;             // 1563 (4 edges/thread)
    int gemmB = (nodes + 127) / 128;            // 391

    scatter_kernel<<<degB, 256>>>(ei, E);
    gemm1_kernel<<<gemmB, 256>>>(x, W1, nodes);
    gather1_gemm2_kernel<<<(nodes + 63) / 64, 512>>>(b1, W2, nodes);
    gather2_final_kernel<<<(nodes + 127) / 128, 512>>>(b2, Wh, bh, out, nodes);
}